// round 12
// baseline (speedup 1.0000x reference)
#include <cuda_runtime.h>
#include <cuda_bf16.h>
#include <math.h>
#include <stdint.h>

// ---------------------------------------------------------------------------
// EdgeMLPMPN via mma.sync bf16x3-split (hi*hi + hi*lo + lo*hi, fp32 acc).
// R12: occupancy push. EPT=32 -> A tile 33.8KB, total ~73KB -> 3 CTAs/SM
// (24 warps/SM vs 16). Warp tile 16e x 32ch (acc 16 regs) to fit the
// 84-reg/thread cap of launch_bounds(256,3). Phase structure as R11.
// ---------------------------------------------------------------------------

#define EPT 32
#define THREADS 256
#define NMAX 100000
#define SA1 528   // A1 row stride bytes (256 bf16 + pad)
#define SA2 272   // h1 row stride (128 bf16 + pad)
#define SWS 144   // W chunk row stride (64 bf16 + pad)

#define SM_A_HI 0
#define SM_A_LO 16896                  // 32*528
#define SM_W_HI 33792
#define SM_W_LO 52224                  // +128*144
#define SM_CTRL 70656
#define SM_SIDS (SM_CTRL)              // 64 ints
#define SM_B1   (SM_CTRL + 256)
#define SM_B2   (SM_B1 + 512)
#define SM_W3   (SM_B2 + 512)
#define SM_RED  (SM_W3 + 512)          // 4 x 32 floats
#define SMEM_BYTES (SM_RED + 512)      // 72960 B -> 3 CTAs/SM

__device__ int g_is64;
__device__ __align__(16) __nv_bfloat16 g_x_hi[NMAX * 128];
__device__ __align__(16) __nv_bfloat16 g_x_lo[NMAX * 128];
__device__ __align__(16) __nv_bfloat16 g_w1t_hi[128 * 256];
__device__ __align__(16) __nv_bfloat16 g_w1t_lo[128 * 256];
__device__ __align__(16) __nv_bfloat16 g_w2t_hi[128 * 128];
__device__ __align__(16) __nv_bfloat16 g_w2t_lo[128 * 128];

__device__ __forceinline__ uint32_t smem_u32(const void* p) {
    uint32_t a;
    asm("{ .reg .u64 t; cvta.to.shared.u64 t, %1; cvt.u32.u64 %0, t; }" : "=r"(a) : "l"(p));
    return a;
}
__device__ __forceinline__ void ldm_x4(uint32_t addr, uint32_t r[4]) {
    asm volatile("ldmatrix.sync.aligned.m8n8.x4.shared.b16 {%0,%1,%2,%3}, [%4];"
                 : "=r"(r[0]), "=r"(r[1]), "=r"(r[2]), "=r"(r[3]) : "r"(addr));
}
__device__ __forceinline__ void hmma(float c[4], const uint32_t a[4],
                                     uint32_t b0, uint32_t b1) {
    asm volatile(
        "mma.sync.aligned.m16n8k16.row.col.f32.bf16.bf16.f32 "
        "{%0,%1,%2,%3}, {%4,%5,%6,%7}, {%8,%9}, {%0,%1,%2,%3};"
        : "+f"(c[0]), "+f"(c[1]), "+f"(c[2]), "+f"(c[3])
        : "r"(a[0]), "r"(a[1]), "r"(a[2]), "r"(a[3]), "r"(b0), "r"(b1));
}
__device__ __forceinline__ void cp16(uint32_t dst, const void* src) {
    asm volatile("cp.async.cg.shared.global [%0], [%1], 16;" :: "r"(dst), "l"(src));
}
__device__ __forceinline__ void cp_commit() {
    asm volatile("cp.async.commit_group;" ::: "memory");
}
__device__ __forceinline__ void cp_wait0() {
    asm volatile("cp.async.wait_group 0;" ::: "memory");
}
__device__ __forceinline__ float elu1(float v) { return v > 0.0f ? v : expm1f(v); }
__device__ __forceinline__ void split_bf16(float v, __nv_bfloat16& hi, __nv_bfloat16& lo) {
    hi = __float2bfloat16_rn(v);
    lo = __float2bfloat16_rn(v - __bfloat162float(hi));
}
union BF4 { __nv_bfloat16 b[4]; unsigned long long u; };
union BF2 { __nv_bfloat16 b[2]; uint32_t u; };

// ---------------- prologue A: split x into bf16 hi/lo ----------------
__global__ void xsplit_kernel(const float* __restrict__ x, int n4) {
    int i = blockIdx.x * blockDim.x + threadIdx.x;
    if (i >= n4) return;
    float4 v = __ldg(reinterpret_cast<const float4*>(x) + i);
    BF4 h, l;
    split_bf16(v.x, h.b[0], l.b[0]);
    split_bf16(v.y, h.b[1], l.b[1]);
    split_bf16(v.z, h.b[2], l.b[2]);
    split_bf16(v.w, h.b[3], l.b[3]);
    *reinterpret_cast<unsigned long long*>(g_x_hi + i * 4) = h.u;
    *reinterpret_cast<unsigned long long*>(g_x_lo + i * 4) = l.u;
}

// ---------------- prologue B: transpose + split W1, W2; sniff ei dtype ----
__global__ void wconv_kernel(const float* __restrict__ W1, const float* __restrict__ W2,
                             const int* __restrict__ ei32) {
    int i = blockIdx.x * blockDim.x + threadIdx.x;
    if (i == 0) {
        int odd_or = 0;
#pragma unroll
        for (int j = 1; j < 64; j += 2) odd_or |= ei32[j];
        g_is64 = (odd_or == 0) ? 1 : 0;
    }
    if (i < 32768) {                     // W1T[n][k] <- W1[k][n]
        int n = i >> 8, k = i & 255;
        float v = __ldg(W1 + k * 128 + n);
        __nv_bfloat16 h, l; split_bf16(v, h, l);
        g_w1t_hi[i] = h; g_w1t_lo[i] = l;
    } else if (i < 49152) {              // W2T[n][k] <- W2[k][n]
        int j = i - 32768;
        int n = j >> 7, k = j & 127;
        float v = __ldg(W2 + k * 128 + n);
        __nv_bfloat16 h, l; split_bf16(v, h, l);
        g_w2t_hi[j] = h; g_w2t_lo[j] = l;
    }
}

// async-stage one [128 n][64 k] hi/lo W chunk
__device__ __forceinline__ void stage_w_async(uint32_t sb,
                                              const __nv_bfloat16* __restrict__ gh,
                                              const __nv_bfloat16* __restrict__ gl,
                                              int row_elems, int col0, int tid) {
#pragma unroll
    for (int it = 0; it < 4; it++) {
        int idx = tid + it * THREADS;
        int n = idx >> 3, j = idx & 7;
        cp16(sb + SM_W_HI + n * SWS + j * 16, gh + n * row_elems + col0 + j * 8);
        cp16(sb + SM_W_LO + n * SWS + j * 16, gl + n * row_elems + col0 + j * 8);
    }
    cp_commit();
}

// one 64-k stage (4 k-tiles); warp tile 1m(16e) x 4n(32ch)
__device__ __forceinline__ void gemm_stage(uint32_t sb, int sa, int a_k0byte,
                                           int e0, int n0, int lane,
                                           float acc[4][4]) {
    const int rowA = lane & 15;
    const int chA = (lane >> 4) * 16;
    const int rowB = (lane & 7) + ((lane >> 4) << 3);
    const int chB = ((lane >> 3) & 1) * 16;

    uint32_t aH = sb + SM_A_HI + (e0 + rowA) * sa + chA + a_k0byte;
    uint32_t aL = sb + SM_A_LO + (e0 + rowA) * sa + chA + a_k0byte;
    uint32_t bH0 = sb + SM_W_HI + (n0 + rowB) * SWS + chB;
    uint32_t bH1 = bH0 + 16 * SWS;
    uint32_t bL0 = sb + SM_W_LO + (n0 + rowB) * SWS + chB;
    uint32_t bL1 = bL0 + 16 * SWS;

#pragma unroll
    for (int kt = 0; kt < 4; kt++) {
        uint32_t ah[4], al[4];
        ldm_x4(aH + kt * 32, ah);
        ldm_x4(aL + kt * 32, al);
        uint32_t bh0[4], bh1[4], bl0[4], bl1[4];
        ldm_x4(bH0 + kt * 32, bh0);
        ldm_x4(bH1 + kt * 32, bh1);
        ldm_x4(bL0 + kt * 32, bl0);
        ldm_x4(bL1 + kt * 32, bl1);
        // pass hh
        hmma(acc[0], ah, bh0[0], bh0[1]);
        hmma(acc[1], ah, bh0[2], bh0[3]);
        hmma(acc[2], ah, bh1[0], bh1[1]);
        hmma(acc[3], ah, bh1[2], bh1[3]);
        // pass hl
        hmma(acc[0], ah, bl0[0], bl0[1]);
        hmma(acc[1], ah, bl0[2], bl0[3]);
        hmma(acc[2], ah, bl1[0], bl1[1]);
        hmma(acc[3], ah, bl1[2], bl1[3]);
        // pass lh
        hmma(acc[0], al, bh0[0], bh0[1]);
        hmma(acc[1], al, bh0[2], bh0[3]);
        hmma(acc[2], al, bh1[0], bh1[1]);
        hmma(acc[3], al, bh1[2], bh1[3]);
    }
}

__global__ void __launch_bounds__(THREADS, 3)
edge_mlp_hmma_kernel(const void* __restrict__ ei,
                     const float* __restrict__ b1, const float* __restrict__ b2,
                     const float* __restrict__ W3, const float* __restrict__ b3,
                     float* __restrict__ out, int n_edges, int n_nodes) {
    extern __shared__ char smem[];
    const uint32_t sb = smem_u32(smem);
    const int tid = threadIdx.x, wid = tid >> 5, lane = tid & 31;
    const int gid = lane >> 2, tig = lane & 3;
    const int mw = wid >> 2, nw = wid & 3;     // 2 x 4 warp grid
    const int e0 = mw * 16, n0 = nw * 32;
    const int tile = blockIdx.x * EPT;
    const int nv = min(EPT, n_edges - tile);

    const bool is64 = (g_is64 != 0);
    const int* ei32 = (const int*)ei;
    const long long* ei64 = (const long long*)ei;

    int* sids = (int*)(smem + SM_SIDS);
    float* b1s = (float*)(smem + SM_B1);
    float* b2s = (float*)(smem + SM_B2);
    float* w3s = (float*)(smem + SM_W3);
    const int ncl = min(n_nodes, NMAX);
    if (tid < 64) {
        int half = tid >> 5, e = tid & 31;
        int ec = e < nv ? e : (nv - 1);
        int pos = half * n_edges + tile + ec;
        long long node = is64 ? ei64[pos] : (long long)ei32[pos];
        node = node < 0 ? 0 : (node >= ncl ? (long long)ncl - 1 : node);
        sids[tid] = (int)node;
    }
    if (tid < 128) {
        b1s[tid] = __ldg(b1 + tid);
        b2s[tid] = __ldg(b2 + tid);
        w3s[tid] = __ldg(W3 + tid);
    }
    __syncthreads();

    // ---- A tile staging: pure cp.async from precomputed g_x_hi/lo ----
#pragma unroll
    for (int it = 0; it < 4; it++) {
        int c = tid + it * THREADS;        // 0..1023
        int j = c & 15, half = (c >> 4) & 1, e = c >> 5;
        int node = sids[half * 32 + e];
        int src = node * 128 + j * 8;
        uint32_t dst = e * SA1 + half * 256 + j * 16;
        cp16(sb + SM_A_HI + dst, g_x_hi + src);
        cp16(sb + SM_A_LO + dst, g_x_lo + src);
    }
    cp_commit();

    // prefetch W1 chunk 0
    stage_w_async(sb, g_w1t_hi, g_w1t_lo, 256, 0, tid);

    cp_wait0();
    __syncthreads();

    float acc[4][4];
#pragma unroll
    for (int j = 0; j < 4; j++)
#pragma unroll
        for (int q = 0; q < 4; q++) acc[j][q] = 0.0f;

    // ---- layer 1: four 64-k stages ----
#pragma unroll 1
    for (int c = 0; c < 4; c++) {
        gemm_stage(sb, SA1, c * 128, e0, n0, lane, acc);
        __syncthreads();
        if (c < 3) {
            stage_w_async(sb, g_w1t_hi, g_w1t_lo, 256, (c + 1) * 64, tid);
            cp_wait0();
            __syncthreads();
        }
    }

    // prefetch W2 chunk 0; overlap with epilogue-1 resplit
    stage_w_async(sb, g_w2t_hi, g_w2t_lo, 128, 0, tid);

    // ---- epilogue 1: bias + elu, re-split h1 into A region (stride SA2) ----
#pragma unroll
    for (int nt = 0; nt < 4; nt++) {
        int nc = n0 + 8 * nt + 2 * tig;
        int ea = e0 + gid, eb = ea + 8;
        float v00 = elu1(acc[nt][0] + b1s[nc]);
        float v01 = elu1(acc[nt][1] + b1s[nc + 1]);
        float v10 = elu1(acc[nt][2] + b1s[nc]);
        float v11 = elu1(acc[nt][3] + b1s[nc + 1]);
        BF2 h, l;
        split_bf16(v00, h.b[0], l.b[0]);
        split_bf16(v01, h.b[1], l.b[1]);
        *reinterpret_cast<uint32_t*>(smem + SM_A_HI + ea * SA2 + nc * 2) = h.u;
        *reinterpret_cast<uint32_t*>(smem + SM_A_LO + ea * SA2 + nc * 2) = l.u;
        split_bf16(v10, h.b[0], l.b[0]);
        split_bf16(v11, h.b[1], l.b[1]);
        *reinterpret_cast<uint32_t*>(smem + SM_A_HI + eb * SA2 + nc * 2) = h.u;
        *reinterpret_cast<uint32_t*>(smem + SM_A_LO + eb * SA2 + nc * 2) = l.u;
    }
#pragma unroll
    for (int j = 0; j < 4; j++)
#pragma unroll
        for (int q = 0; q < 4; q++) acc[j][q] = 0.0f;
    cp_wait0();
    __syncthreads();

    // ---- layer 2: two 64-k stages ----
#pragma unroll 1
    for (int c = 0; c < 2; c++) {
        gemm_stage(sb, SA2, c * 128, e0, n0, lane, acc);
        __syncthreads();
        if (c == 0) {
            stage_w_async(sb, g_w2t_hi, g_w2t_lo, 128, 64, tid);
            cp_wait0();
            __syncthreads();
        }
    }

    // ---- epilogue 2: bias + elu + dot(W3), butterfly over tig ----
    float pa = 0.0f, pb = 0.0f;
#pragma unroll
    for (int nt = 0; nt < 4; nt++) {
        int nc = n0 + 8 * nt + 2 * tig;
        float w0 = w3s[nc], w1 = w3s[nc + 1];
        pa += elu1(acc[nt][0] + b2s[nc]) * w0 + elu1(acc[nt][1] + b2s[nc + 1]) * w1;
        pb += elu1(acc[nt][2] + b2s[nc]) * w0 + elu1(acc[nt][3] + b2s[nc + 1]) * w1;
    }
    pa += __shfl_xor_sync(0xffffffff, pa, 1);
    pa += __shfl_xor_sync(0xffffffff, pa, 2);
    pb += __shfl_xor_sync(0xffffffff, pb, 1);
    pb += __shfl_xor_sync(0xffffffff, pb, 2);
    float* red = (float*)(smem + SM_RED);
    if (tig == 0) {
        red[nw * 32 + e0 + gid] = pa;
        red[nw * 32 + e0 + gid + 8] = pb;
    }
    __syncthreads();
    if (tid < 32 && tid < nv) {
        out[tile + tid] = red[tid] + red[32 + tid] + red[64 + tid] + red[96 + tid]
                        + __ldg(b3);
    }
}

extern "C" void kernel_launch(void* const* d_in, const int* in_sizes, int n_in,
                              void* d_out, int out_size) {
    const float* x  = (const float*)d_in[0];
    const void*  ei = d_in[1];
    const float* W1 = (const float*)d_in[2];
    const float* b1 = (const float*)d_in[3];
    const float* W2 = (const float*)d_in[4];
    const float* b2 = (const float*)d_in[5];
    const float* W3 = (const float*)d_in[6];
    const float* b3 = (const float*)d_in[7];
    float* out = (float*)d_out;

    const int n_edges = out_size;
    const int n_nodes = in_sizes[0] / 128;
    const int n4 = (n_nodes < NMAX ? n_nodes : NMAX) * 128 / 4;

    cudaFuncSetAttribute(edge_mlp_hmma_kernel,
                         cudaFuncAttributeMaxDynamicSharedMemorySize, SMEM_BYTES);

    wconv_kernel<<<192, 256>>>(W1, W2, (const int*)ei);
    xsplit_kernel<<<(n4 + 255) / 256, 256>>>(x, n4);
    const int grid = (n_edges + EPT - 1) / EPT;
    edge_mlp_hmma_kernel<<<grid, THREADS, SMEM_BYTES>>>(ei, b1, b2, W3, b3,
                                                        out, n_edges, n_nodes);
}

// round 14
// speedup vs baseline: 1.2750x; 1.2750x over previous
#include <cuda_runtime.h>
#include <cuda_bf16.h>
#include <math.h>
#include <stdint.h>

// ---------------------------------------------------------------------------
// EdgeMLPMPN via mma.sync bf16x3-split (hi*hi + hi*lo + lo*hi, fp32 acc).
// R14 = R11 (best: 650us) with ELU computed via fast __expf (MUFU.EX2)
// instead of libdevice expm1f. EPT=64, 2 CTAs/SM, 8 warps (2m x 4n),
// x pre-split to bf16 hi/lo, W transposed+split in prologue, cp.async gather.
// ---------------------------------------------------------------------------

#define EPT 64
#define THREADS 256
#define NMAX 100000
#define SA1 528   // A1 row stride bytes (256 bf16 + pad); ldmatrix conflict-free
#define SA2 272   // h1 row stride (128 bf16 + pad)
#define SWS 144   // W chunk row stride (64 bf16 + pad)

#define SM_A_HI 0
#define SM_A_LO 33792                  // 64*528
#define SM_W_HI 67584
#define SM_W_LO (SM_W_HI + 18432)      // 128*144
#define SM_CTRL (SM_W_LO + 18432)      // 104448
#define SM_SIDS (SM_CTRL)              // 128 ints
#define SM_B1   (SM_CTRL + 512)
#define SM_B2   (SM_B1 + 512)
#define SM_W3   (SM_B2 + 512)
#define SM_RED  (SM_W3 + 512)          // 4 x 64 floats
#define SMEM_BYTES (SM_RED + 1024)     // ~105KB -> 2 CTAs/SM

__device__ int g_is64;
__device__ __align__(16) __nv_bfloat16 g_x_hi[NMAX * 128];
__device__ __align__(16) __nv_bfloat16 g_x_lo[NMAX * 128];
__device__ __align__(16) __nv_bfloat16 g_w1t_hi[128 * 256];
__device__ __align__(16) __nv_bfloat16 g_w1t_lo[128 * 256];
__device__ __align__(16) __nv_bfloat16 g_w2t_hi[128 * 128];
__device__ __align__(16) __nv_bfloat16 g_w2t_lo[128 * 128];

__device__ __forceinline__ uint32_t smem_u32(const void* p) {
    uint32_t a;
    asm("{ .reg .u64 t; cvta.to.shared.u64 t, %1; cvt.u32.u64 %0, t; }" : "=r"(a) : "l"(p));
    return a;
}
__device__ __forceinline__ void ldm_x4(uint32_t addr, uint32_t r[4]) {
    asm volatile("ldmatrix.sync.aligned.m8n8.x4.shared.b16 {%0,%1,%2,%3}, [%4];"
                 : "=r"(r[0]), "=r"(r[1]), "=r"(r[2]), "=r"(r[3]) : "r"(addr));
}
__device__ __forceinline__ void hmma(float c[4], const uint32_t a[4],
                                     uint32_t b0, uint32_t b1) {
    asm volatile(
        "mma.sync.aligned.m16n8k16.row.col.f32.bf16.bf16.f32 "
        "{%0,%1,%2,%3}, {%4,%5,%6,%7}, {%8,%9}, {%0,%1,%2,%3};"
        : "+f"(c[0]), "+f"(c[1]), "+f"(c[2]), "+f"(c[3])
        : "r"(a[0]), "r"(a[1]), "r"(a[2]), "r"(a[3]), "r"(b0), "r"(b1));
}
__device__ __forceinline__ void cp16(uint32_t dst, const void* src) {
    asm volatile("cp.async.cg.shared.global [%0], [%1], 16;" :: "r"(dst), "l"(src));
}
__device__ __forceinline__ void cp_commit() {
    asm volatile("cp.async.commit_group;" ::: "memory");
}
__device__ __forceinline__ void cp_wait0() {
    asm volatile("cp.async.wait_group 0;" ::: "memory");
}
// fast ELU: exp via MUFU.EX2 (error ~2^-21, negligible vs 6e-6 budget)
__device__ __forceinline__ float elu1(float v) {
    return v > 0.0f ? v : (__expf(v) - 1.0f);
}
__device__ __forceinline__ void split_bf16(float v, __nv_bfloat16& hi, __nv_bfloat16& lo) {
    hi = __float2bfloat16_rn(v);
    lo = __float2bfloat16_rn(v - __bfloat162float(hi));
}
union BF4 { __nv_bfloat16 b[4]; unsigned long long u; };
union BF2 { __nv_bfloat16 b[2]; uint32_t u; };

// ---------------- prologue A: split x into bf16 hi/lo ----------------
__global__ void xsplit_kernel(const float* __restrict__ x, int n4) {
    int i = blockIdx.x * blockDim.x + threadIdx.x;
    if (i >= n4) return;
    float4 v = __ldg(reinterpret_cast<const float4*>(x) + i);
    BF4 h, l;
    split_bf16(v.x, h.b[0], l.b[0]);
    split_bf16(v.y, h.b[1], l.b[1]);
    split_bf16(v.z, h.b[2], l.b[2]);
    split_bf16(v.w, h.b[3], l.b[3]);
    *reinterpret_cast<unsigned long long*>(g_x_hi + i * 4) = h.u;
    *reinterpret_cast<unsigned long long*>(g_x_lo + i * 4) = l.u;
}

// ---------------- prologue B: transpose + split W1, W2; sniff ei dtype ----
__global__ void wconv_kernel(const float* __restrict__ W1, const float* __restrict__ W2,
                             const int* __restrict__ ei32) {
    int i = blockIdx.x * blockDim.x + threadIdx.x;
    if (i == 0) {
        int odd_or = 0;
#pragma unroll
        for (int j = 1; j < 64; j += 2) odd_or |= ei32[j];
        g_is64 = (odd_or == 0) ? 1 : 0;
    }
    if (i < 32768) {                     // W1T[n][k] <- W1[k][n]
        int n = i >> 8, k = i & 255;
        float v = __ldg(W1 + k * 128 + n);
        __nv_bfloat16 h, l; split_bf16(v, h, l);
        g_w1t_hi[i] = h; g_w1t_lo[i] = l;
    } else if (i < 49152) {              // W2T[n][k] <- W2[k][n]
        int j = i - 32768;
        int n = j >> 7, k = j & 127;
        float v = __ldg(W2 + k * 128 + n);
        __nv_bfloat16 h, l; split_bf16(v, h, l);
        g_w2t_hi[j] = h; g_w2t_lo[j] = l;
    }
}

// async-stage one [128 n][64 k] hi/lo W chunk
__device__ __forceinline__ void stage_w_async(uint32_t sb,
                                              const __nv_bfloat16* __restrict__ gh,
                                              const __nv_bfloat16* __restrict__ gl,
                                              int row_elems, int col0, int tid) {
#pragma unroll
    for (int it = 0; it < 4; it++) {
        int idx = tid + it * THREADS;
        int n = idx >> 3, j = idx & 7;
        cp16(sb + SM_W_HI + n * SWS + j * 16, gh + n * row_elems + col0 + j * 8);
        cp16(sb + SM_W_LO + n * SWS + j * 16, gl + n * row_elems + col0 + j * 8);
    }
    cp_commit();
}

// one 64-k stage (4 k-tiles); warp tile 2m x 4n; pass-major schedule
__device__ __forceinline__ void gemm_stage(uint32_t sb, int sa, int a_k0byte,
                                           int e0, int n0, int lane,
                                           float acc[2][4][4]) {
    const int rowA = lane & 15;
    const int chA = (lane >> 4) * 16;
    const int rowB = (lane & 7) + ((lane >> 4) << 3);
    const int chB = ((lane >> 3) & 1) * 16;

    uint32_t aH0 = sb + SM_A_HI + (e0 + rowA) * sa + chA + a_k0byte;
    uint32_t aH1 = aH0 + 16 * sa;
    uint32_t aL0 = sb + SM_A_LO + (e0 + rowA) * sa + chA + a_k0byte;
    uint32_t aL1 = aL0 + 16 * sa;
    uint32_t bH0 = sb + SM_W_HI + (n0 + rowB) * SWS + chB;
    uint32_t bH1 = bH0 + 16 * SWS;
    uint32_t bL0 = sb + SM_W_LO + (n0 + rowB) * SWS + chB;
    uint32_t bL1 = bL0 + 16 * SWS;

#pragma unroll
    for (int kt = 0; kt < 4; kt++) {
        uint32_t ah0[4], ah1[4], al0[4], al1[4];
        ldm_x4(aH0 + kt * 32, ah0);
        ldm_x4(aH1 + kt * 32, ah1);
        ldm_x4(aL0 + kt * 32, al0);
        ldm_x4(aL1 + kt * 32, al1);
        uint32_t bh0[4], bh1[4], bl0[4], bl1[4];
        ldm_x4(bH0 + kt * 32, bh0);
        ldm_x4(bH1 + kt * 32, bh1);
        ldm_x4(bL0 + kt * 32, bl0);
        ldm_x4(bL1 + kt * 32, bl1);
        // pass hh
        hmma(acc[0][0], ah0, bh0[0], bh0[1]);
        hmma(acc[0][1], ah0, bh0[2], bh0[3]);
        hmma(acc[0][2], ah0, bh1[0], bh1[1]);
        hmma(acc[0][3], ah0, bh1[2], bh1[3]);
        hmma(acc[1][0], ah1, bh0[0], bh0[1]);
        hmma(acc[1][1], ah1, bh0[2], bh0[3]);
        hmma(acc[1][2], ah1, bh1[0], bh1[1]);
        hmma(acc[1][3], ah1, bh1[2], bh1[3]);
        // pass hl
        hmma(acc[0][0], ah0, bl0[0], bl0[1]);
        hmma(acc[0][1], ah0, bl0[2], bl0[3]);
        hmma(acc[0][2], ah0, bl1[0], bl1[1]);
        hmma(acc[0][3], ah0, bl1[2], bl1[3]);
        hmma(acc[1][0], ah1, bl0[0], bl0[1]);
        hmma(acc[1][1], ah1, bl0[2], bl0[3]);
        hmma(acc[1][2], ah1, bl1[0], bl1[1]);
        hmma(acc[1][3], ah1, bl1[2], bl1[3]);
        // pass lh
        hmma(acc[0][0], al0, bh0[0], bh0[1]);
        hmma(acc[0][1], al0, bh0[2], bh0[3]);
        hmma(acc[0][2], al0, bh1[0], bh1[1]);
        hmma(acc[0][3], al0, bh1[2], bh1[3]);
        hmma(acc[1][0], al1, bh0[0], bh0[1]);
        hmma(acc[1][1], al1, bh0[2], bh0[3]);
        hmma(acc[1][2], al1, bh1[0], bh1[1]);
        hmma(acc[1][3], al1, bh1[2], bh1[3]);
    }
}

__global__ void __launch_bounds__(THREADS, 2)
edge_mlp_hmma_kernel(const void* __restrict__ ei,
                     const float* __restrict__ b1, const float* __restrict__ b2,
                     const float* __restrict__ W3, const float* __restrict__ b3,
                     float* __restrict__ out, int n_edges, int n_nodes) {
    extern __shared__ char smem[];
    const uint32_t sb = smem_u32(smem);
    const int tid = threadIdx.x, wid = tid >> 5, lane = tid & 31;
    const int gid = lane >> 2, tig = lane & 3;
    const int mw = wid >> 2, nw = wid & 3;     // 2 x 4 warp grid
    const int e0 = mw * 32, n0 = nw * 32;
    const int tile = blockIdx.x * EPT;
    const int nv = min(EPT, n_edges - tile);

    const bool is64 = (g_is64 != 0);
    const int* ei32 = (const int*)ei;
    const long long* ei64 = (const long long*)ei;

    int* sids = (int*)(smem + SM_SIDS);
    float* b1s = (float*)(smem + SM_B1);
    float* b2s = (float*)(smem + SM_B2);
    float* w3s = (float*)(smem + SM_W3);
    const int ncl = min(n_nodes, NMAX);
    if (tid < 128) {
        int half = tid >> 6, e = tid & 63;
        int ec = e < nv ? e : (nv - 1);
        int pos = half * n_edges + tile + ec;
        long long node = is64 ? ei64[pos] : (long long)ei32[pos];
        node = node < 0 ? 0 : (node >= ncl ? (long long)ncl - 1 : node);
        sids[tid] = (int)node;
        b1s[tid] = __ldg(b1 + tid);
        b2s[tid] = __ldg(b2 + tid);
        w3s[tid] = __ldg(W3 + tid);
    }
    __syncthreads();

    // ---- A tile staging: pure cp.async from precomputed g_x_hi/lo ----
#pragma unroll
    for (int it = 0; it < 8; it++) {
        int c = tid + it * THREADS;        // 0..2047
        int j = c & 15, half = (c >> 4) & 1, e = c >> 5;
        int node = sids[half * 64 + e];
        int src = node * 128 + j * 8;
        uint32_t dst = e * SA1 + half * 256 + j * 16;
        cp16(sb + SM_A_HI + dst, g_x_hi + src);
        cp16(sb + SM_A_LO + dst, g_x_lo + src);
    }
    cp_commit();

    // prefetch W1 chunk 0 (own commit group)
    stage_w_async(sb, g_w1t_hi, g_w1t_lo, 256, 0, tid);

    cp_wait0();
    __syncthreads();

    float acc[2][4][4];
#pragma unroll
    for (int m = 0; m < 2; m++)
#pragma unroll
        for (int j = 0; j < 4; j++)
#pragma unroll
            for (int q = 0; q < 4; q++) acc[m][j][q] = 0.0f;

    // ---- layer 1: four 64-k stages ----
#pragma unroll 1
    for (int c = 0; c < 4; c++) {
        gemm_stage(sb, SA1, c * 128, e0, n0, lane, acc);
        __syncthreads();
        if (c < 3) {
            stage_w_async(sb, g_w1t_hi, g_w1t_lo, 256, (c + 1) * 64, tid);
            cp_wait0();
            __syncthreads();
        }
    }

    // prefetch W2 chunk 0; overlap with epilogue-1 resplit
    stage_w_async(sb, g_w2t_hi, g_w2t_lo, 128, 0, tid);

    // ---- epilogue 1: bias + elu, re-split h1 into A region (stride SA2) ----
#pragma unroll
    for (int mt = 0; mt < 2; mt++) {
#pragma unroll
        for (int nt = 0; nt < 4; nt++) {
            int nc = n0 + 8 * nt + 2 * tig;
            int ea = e0 + 16 * mt + gid, eb = ea + 8;
            float v00 = elu1(acc[mt][nt][0] + b1s[nc]);
            float v01 = elu1(acc[mt][nt][1] + b1s[nc + 1]);
            float v10 = elu1(acc[mt][nt][2] + b1s[nc]);
            float v11 = elu1(acc[mt][nt][3] + b1s[nc + 1]);
            BF2 h, l;
            split_bf16(v00, h.b[0], l.b[0]);
            split_bf16(v01, h.b[1], l.b[1]);
            *reinterpret_cast<uint32_t*>(smem + SM_A_HI + ea * SA2 + nc * 2) = h.u;
            *reinterpret_cast<uint32_t*>(smem + SM_A_LO + ea * SA2 + nc * 2) = l.u;
            split_bf16(v10, h.b[0], l.b[0]);
            split_bf16(v11, h.b[1], l.b[1]);
            *reinterpret_cast<uint32_t*>(smem + SM_A_HI + eb * SA2 + nc * 2) = h.u;
            *reinterpret_cast<uint32_t*>(smem + SM_A_LO + eb * SA2 + nc * 2) = l.u;
        }
    }
#pragma unroll
    for (int m = 0; m < 2; m++)
#pragma unroll
        for (int j = 0; j < 4; j++)
#pragma unroll
            for (int q = 0; q < 4; q++) acc[m][j][q] = 0.0f;
    cp_wait0();
    __syncthreads();

    // ---- layer 2: two 64-k stages ----
#pragma unroll 1
    for (int c = 0; c < 2; c++) {
        gemm_stage(sb, SA2, c * 128, e0, n0, lane, acc);
        __syncthreads();
        if (c == 0) {
            stage_w_async(sb, g_w2t_hi, g_w2t_lo, 128, 64, tid);
            cp_wait0();
            __syncthreads();
        }
    }

    // ---- epilogue 2: bias + elu + dot(W3), butterfly over tig ----
    float pa[2] = {0.0f, 0.0f}, pb[2] = {0.0f, 0.0f};
#pragma unroll
    for (int mt = 0; mt < 2; mt++) {
#pragma unroll
        for (int nt = 0; nt < 4; nt++) {
            int nc = n0 + 8 * nt + 2 * tig;
            float w0 = w3s[nc], w1 = w3s[nc + 1];
            pa[mt] += elu1(acc[mt][nt][0] + b2s[nc]) * w0
                    + elu1(acc[mt][nt][1] + b2s[nc + 1]) * w1;
            pb[mt] += elu1(acc[mt][nt][2] + b2s[nc]) * w0
                    + elu1(acc[mt][nt][3] + b2s[nc + 1]) * w1;
        }
    }
#pragma unroll
    for (int mt = 0; mt < 2; mt++) {
        pa[mt] += __shfl_xor_sync(0xffffffff, pa[mt], 1);
        pa[mt] += __shfl_xor_sync(0xffffffff, pa[mt], 2);
        pb[mt] += __shfl_xor_sync(0xffffffff, pb[mt], 1);
        pb[mt] += __shfl_xor_sync(0xffffffff, pb[mt], 2);
    }
    float* red = (float*)(smem + SM_RED) + nw * 64;
    if (tig == 0) {
#pragma unroll
        for (int mt = 0; mt < 2; mt++) {
            red[e0 + 16 * mt + gid] = pa[mt];
            red[e0 + 16 * mt + gid + 8] = pb[mt];
        }
    }
    __syncthreads();
    if (tid < 64 && tid < nv) {
        float* r = (float*)(smem + SM_RED);
        out[tile + tid] = r[tid] + r[64 + tid] + r[128 + tid] + r[192 + tid] + __ldg(b3);
    }
}

extern "C" void kernel_launch(void* const* d_in, const int* in_sizes, int n_in,
                              void* d_out, int out_size) {
    const float* x  = (const float*)d_in[0];
    const void*  ei = d_in[1];
    const float* W1 = (const float*)d_in[2];
    const float* b1 = (const float*)d_in[3];
    const float* W2 = (const float*)d_in[4];
    const float* b2 = (const float*)d_in[5];
    const float* W3 = (const float*)d_in[6];
    const float* b3 = (const float*)d_in[7];
    float* out = (float*)d_out;

    const int n_edges = out_size;
    const int n_nodes = in_sizes[0] / 128;
    const int n4 = (n_nodes < NMAX ? n_nodes : NMAX) * 128 / 4;

    cudaFuncSetAttribute(edge_mlp_hmma_kernel,
                         cudaFuncAttributeMaxDynamicSharedMemorySize, SMEM_BYTES);

    wconv_kernel<<<192, 256>>>(W1, W2, (const int*)ei);
    xsplit_kernel<<<(n4 + 255) / 256, 256>>>(x, n4);
    const int grid = (n_edges + EPT - 1) / EPT;
    edge_mlp_hmma_kernel<<<grid, THREADS, SMEM_BYTES>>>(ei, b1, b2, W3, b3,
                                                        out, n_edges, n_nodes);
}

// round 16
// speedup vs baseline: 1.6699x; 1.3097x over previous
#include <cuda_runtime.h>
#include <cuda_bf16.h>
#include <math.h>
#include <stdint.h>

// ---------------------------------------------------------------------------
// EdgeMLPMPN, R16 = R15 with the pq_kernel A-staging fix (full 256B rows).
//   P = x @ W1[0:128] + b1,  Q = x @ W1[128:256]      (per node, prologue)
//   h1 = elu(P[src] + Q[tgt])                          (per edge, gather+add)
//   h2 = elu(h1 @ W2 + b2); out = h2 @ W3 + b3         (per edge, bf16x3 HMMA)
// Cuts per-edge tensor work by 2/3. EPT=64, 2 CTAs/SM, 8 warps (2m x 4n).
// ---------------------------------------------------------------------------

#define EPT 64
#define THREADS 256
#define NMAX 100000
#define SA2 272    // A/h1 row stride (128 bf16 + 16B pad)
#define SWS 144    // W chunk row stride (64 bf16 + 16B pad)

// shared layout (main kernel and pq kernel use the same map)
#define SM_A_HI 0
#define SM_A_LO 17408
#define SM_W    34816                  // chunk c: hi @ +c*36864, lo @ hi+18432
#define WCHUNK  36864
#define WLO_OFF 18432
#define SM_CTRL 108544
#define SM_SIDS (SM_CTRL)              // 128 ints  (pq: b1s here)
#define SM_B2   (SM_CTRL + 512)
#define SM_W3   (SM_B2 + 512)
#define SM_RED  (SM_W3 + 512)          // 4 x 64 floats
#define SMEM_BYTES (SM_RED + 1024)     // 111104 B -> 2 CTAs/SM

__device__ int g_is64;
__device__ __align__(16) __nv_bfloat16 g_x_hi[NMAX * 128];
__device__ __align__(16) __nv_bfloat16 g_x_lo[NMAX * 128];
__device__ __align__(16) __nv_bfloat16 g_w1t_hi[128 * 256];
__device__ __align__(16) __nv_bfloat16 g_w1t_lo[128 * 256];
__device__ __align__(16) __nv_bfloat16 g_w2t_hi[128 * 128];
__device__ __align__(16) __nv_bfloat16 g_w2t_lo[128 * 128];
__device__ __align__(16) float g_P[NMAX * 128];   // x@W1a + b1
__device__ __align__(16) float g_Q[NMAX * 128];   // x@W1b

__device__ __forceinline__ uint32_t smem_u32(const void* p) {
    uint32_t a;
    asm("{ .reg .u64 t; cvta.to.shared.u64 t, %1; cvt.u32.u64 %0, t; }" : "=r"(a) : "l"(p));
    return a;
}
__device__ __forceinline__ void ldm_x4(uint32_t addr, uint32_t r[4]) {
    asm volatile("ldmatrix.sync.aligned.m8n8.x4.shared.b16 {%0,%1,%2,%3}, [%4];"
                 : "=r"(r[0]), "=r"(r[1]), "=r"(r[2]), "=r"(r[3]) : "r"(addr));
}
__device__ __forceinline__ void hmma(float c[4], const uint32_t a[4],
                                     uint32_t b0, uint32_t b1) {
    asm volatile(
        "mma.sync.aligned.m16n8k16.row.col.f32.bf16.bf16.f32 "
        "{%0,%1,%2,%3}, {%4,%5,%6,%7}, {%8,%9}, {%0,%1,%2,%3};"
        : "+f"(c[0]), "+f"(c[1]), "+f"(c[2]), "+f"(c[3])
        : "r"(a[0]), "r"(a[1]), "r"(a[2]), "r"(a[3]), "r"(b0), "r"(b1));
}
__device__ __forceinline__ void cp16(uint32_t dst, const void* src) {
    asm volatile("cp.async.cg.shared.global [%0], [%1], 16;" :: "r"(dst), "l"(src));
}
__device__ __forceinline__ void cp_commit() {
    asm volatile("cp.async.commit_group;" ::: "memory");
}
__device__ __forceinline__ void cp_wait0() {
    asm volatile("cp.async.wait_group 0;" ::: "memory");
}
__device__ __forceinline__ float elu1(float v) {
    return v > 0.0f ? v : (__expf(v) - 1.0f);
}
__device__ __forceinline__ void split_bf16(float v, __nv_bfloat16& hi, __nv_bfloat16& lo) {
    hi = __float2bfloat16_rn(v);
    lo = __float2bfloat16_rn(v - __bfloat162float(hi));
}
union BF4 { __nv_bfloat16 b[4]; unsigned long long u; };
union BF2 { __nv_bfloat16 b[2]; uint32_t u; };

// ---------------- prologue A: split x into bf16 hi/lo ----------------
__global__ void xsplit_kernel(const float* __restrict__ x, int n4) {
    int i = blockIdx.x * blockDim.x + threadIdx.x;
    if (i >= n4) return;
    float4 v = __ldg(reinterpret_cast<const float4*>(x) + i);
    BF4 h, l;
    split_bf16(v.x, h.b[0], l.b[0]);
    split_bf16(v.y, h.b[1], l.b[1]);
    split_bf16(v.z, h.b[2], l.b[2]);
    split_bf16(v.w, h.b[3], l.b[3]);
    *reinterpret_cast<unsigned long long*>(g_x_hi + i * 4) = h.u;
    *reinterpret_cast<unsigned long long*>(g_x_lo + i * 4) = l.u;
}

// ---------------- prologue B: transpose + split W1, W2; sniff ei dtype ----
__global__ void wconv_kernel(const float* __restrict__ W1, const float* __restrict__ W2,
                             const int* __restrict__ ei32) {
    int i = blockIdx.x * blockDim.x + threadIdx.x;
    if (i == 0) {
        int odd_or = 0;
#pragma unroll
        for (int j = 1; j < 64; j += 2) odd_or |= ei32[j];
        g_is64 = (odd_or == 0) ? 1 : 0;
    }
    if (i < 32768) {                     // W1T[n][k] <- W1[k][n]
        int n = i >> 8, k = i & 255;
        float v = __ldg(W1 + k * 128 + n);
        __nv_bfloat16 h, l; split_bf16(v, h, l);
        g_w1t_hi[i] = h; g_w1t_lo[i] = l;
    } else if (i < 49152) {              // W2T[n][k] <- W2[k][n]
        int j = i - 32768;
        int n = j >> 7, k = j & 127;
        float v = __ldg(W2 + k * 128 + n);
        __nv_bfloat16 h, l; split_bf16(v, h, l);
        g_w2t_hi[j] = h; g_w2t_lo[j] = l;
    }
}

// shared: one 64-k chunk (4 k-tiles); warp tile 2m x 4n; pass-major schedule.
// aH/aL: smem bases of A hi/lo (row stride sa); wHi: W chunk hi base (lo +18432)
__device__ __forceinline__ void gemm_chunk(uint32_t aH, uint32_t aL, int sa,
                                           int a_k0byte, uint32_t wHi,
                                           int e0, int n0, int lane,
                                           float acc[2][4][4]) {
    const int rowA = lane & 15;
    const int chA = (lane >> 4) * 16;
    const int rowB = (lane & 7) + ((lane >> 4) << 3);
    const int chB = ((lane >> 3) & 1) * 16;

    uint32_t aH0 = aH + (e0 + rowA) * sa + chA + a_k0byte;
    uint32_t aH1 = aH0 + 16 * sa;
    uint32_t aL0 = aL + (e0 + rowA) * sa + chA + a_k0byte;
    uint32_t aL1 = aL0 + 16 * sa;
    uint32_t bH0 = wHi + (n0 + rowB) * SWS + chB;
    uint32_t bH1 = bH0 + 16 * SWS;
    uint32_t bL0 = bH0 + WLO_OFF;
    uint32_t bL1 = bL0 + 16 * SWS;

#pragma unroll
    for (int kt = 0; kt < 4; kt++) {
        uint32_t ah0[4], ah1[4], al0[4], al1[4];
        ldm_x4(aH0 + kt * 32, ah0);
        ldm_x4(aH1 + kt * 32, ah1);
        ldm_x4(aL0 + kt * 32, al0);
        ldm_x4(aL1 + kt * 32, al1);
        uint32_t bh0[4], bh1[4], bl0[4], bl1[4];
        ldm_x4(bH0 + kt * 32, bh0);
        ldm_x4(bH1 + kt * 32, bh1);
        ldm_x4(bL0 + kt * 32, bl0);
        ldm_x4(bL1 + kt * 32, bl1);
        hmma(acc[0][0], ah0, bh0[0], bh0[1]);
        hmma(acc[0][1], ah0, bh0[2], bh0[3]);
        hmma(acc[0][2], ah0, bh1[0], bh1[1]);
        hmma(acc[0][3], ah0, bh1[2], bh1[3]);
        hmma(acc[1][0], ah1, bh0[0], bh0[1]);
        hmma(acc[1][1], ah1, bh0[2], bh0[3]);
        hmma(acc[1][2], ah1, bh1[0], bh1[1]);
        hmma(acc[1][3], ah1, bh1[2], bh1[3]);
        hmma(acc[0][0], ah0, bl0[0], bl0[1]);
        hmma(acc[0][1], ah0, bl0[2], bl0[3]);
        hmma(acc[0][2], ah0, bl1[0], bl1[1]);
        hmma(acc[0][3], ah0, bl1[2], bl1[3]);
        hmma(acc[1][0], ah1, bl0[0], bl0[1]);
        hmma(acc[1][1], ah1, bl0[2], bl0[3]);
        hmma(acc[1][2], ah1, bl1[0], bl1[1]);
        hmma(acc[1][3], ah1, bl1[2], bl1[3]);
        hmma(acc[0][0], al0, bh0[0], bh0[1]);
        hmma(acc[0][1], al0, bh0[2], bh0[3]);
        hmma(acc[0][2], al0, bh1[0], bh1[1]);
        hmma(acc[0][3], al0, bh1[2], bh1[3]);
        hmma(acc[1][0], al1, bh0[0], bh0[1]);
        hmma(acc[1][1], al1, bh0[2], bh0[3]);
        hmma(acc[1][2], al1, bh1[0], bh1[1]);
        hmma(acc[1][3], al1, bh1[2], bh1[3]);
    }
}

// ---------------- prologue C: P = x@W1a + b1, Q = x@W1b (per node) ----------
__global__ void __launch_bounds__(THREADS, 2)
pq_kernel(const float* __restrict__ b1, int n_nodes) {
    extern __shared__ char smem[];
    const uint32_t sb = smem_u32(smem);
    const int tid = threadIdx.x, wid = tid >> 5, lane = tid & 31;
    const int gid = lane >> 2, tig = lane & 3;
    const int mw = wid >> 2, nw = wid & 3;
    const int e0 = mw * 32, n0 = nw * 32;
    const int sel = blockIdx.x & 1;        // 0 -> P, 1 -> Q
    const int tile = blockIdx.x >> 1;
    const int node0 = tile * 64;
    const int ncl = min(n_nodes, NMAX);

    float* b1s = (float*)(smem + SM_SIDS);
    if (tid < 128) b1s[tid] = sel ? 0.0f : __ldg(b1 + tid);

    // stage A: 64 node rows of x (hi/lo), full 128 bf16 = 256 B per row
    // FIX vs R15: 1024 cp16 per buffer (16 x 16B chunks per row), not 512.
#pragma unroll
    for (int it = 0; it < 4; it++) {
        int idx = tid + it * THREADS;      // 0..1023
        int e = idx >> 4, j = idx & 15;
        int node = node0 + e;
        node = node < ncl ? node : (ncl - 1);
        int src = node * 128 + j * 8;
        uint32_t dst = e * SA2 + j * 16;
        cp16(sb + SM_A_HI + dst, g_x_hi + src);
        cp16(sb + SM_A_LO + dst, g_x_lo + src);
    }
    // stage W1 half 'sel' as two 64-k chunks
#pragma unroll
    for (int c = 0; c < 2; c++) {
        uint32_t base = sb + SM_W + (uint32_t)c * WCHUNK;
        int col0 = sel * 128 + c * 64;
#pragma unroll
        for (int it = 0; it < 4; it++) {
            int idx = tid + it * THREADS;  // 0..1023
            int n = idx >> 3, j = idx & 7;
            cp16(base + n * SWS + j * 16, g_w1t_hi + n * 256 + col0 + j * 8);
            cp16(base + WLO_OFF + n * SWS + j * 16, g_w1t_lo + n * 256 + col0 + j * 8);
        }
    }
    cp_commit();
    cp_wait0();
    __syncthreads();

    float acc[2][4][4];
#pragma unroll
    for (int m = 0; m < 2; m++)
#pragma unroll
        for (int j = 0; j < 4; j++)
#pragma unroll
            for (int q = 0; q < 4; q++) acc[m][j][q] = 0.0f;

    gemm_chunk(sb + SM_A_HI, sb + SM_A_LO, SA2, 0,   sb + SM_W,          e0, n0, lane, acc);
    gemm_chunk(sb + SM_A_HI, sb + SM_A_LO, SA2, 128, sb + SM_W + WCHUNK, e0, n0, lane, acc);

    float* outg = sel ? g_Q : g_P;
#pragma unroll
    for (int mt = 0; mt < 2; mt++) {
#pragma unroll
        for (int nt = 0; nt < 4; nt++) {
            int nc = n0 + 8 * nt + 2 * tig;
            int ra = e0 + 16 * mt + gid, rb = ra + 8;
            int ga = node0 + ra, gb = node0 + rb;
            if (ga < ncl) {
                outg[ga * 128 + nc]     = acc[mt][nt][0] + b1s[nc];
                outg[ga * 128 + nc + 1] = acc[mt][nt][1] + b1s[nc + 1];
            }
            if (gb < ncl) {
                outg[gb * 128 + nc]     = acc[mt][nt][2] + b1s[nc];
                outg[gb * 128 + nc + 1] = acc[mt][nt][3] + b1s[nc + 1];
            }
        }
    }
}

// ---------------- main kernel: h1 = elu(P[src]+Q[tgt]); layers 2,3 ----------
__global__ void __launch_bounds__(THREADS, 2)
edge_mlp_hmma_kernel(const void* __restrict__ ei,
                     const float* __restrict__ b2,
                     const float* __restrict__ W3, const float* __restrict__ b3,
                     float* __restrict__ out, int n_edges, int n_nodes) {
    extern __shared__ char smem[];
    const uint32_t sb = smem_u32(smem);
    const int tid = threadIdx.x, wid = tid >> 5, lane = tid & 31;
    const int gid = lane >> 2, tig = lane & 3;
    const int mw = wid >> 2, nw = wid & 3;
    const int e0 = mw * 32, n0 = nw * 32;
    const int tile = blockIdx.x * EPT;
    const int nv = min(EPT, n_edges - tile);

    const bool is64 = (g_is64 != 0);
    const int* ei32 = (const int*)ei;
    const long long* ei64 = (const long long*)ei;

    int* sids = (int*)(smem + SM_SIDS);
    float* b2s = (float*)(smem + SM_B2);
    float* w3s = (float*)(smem + SM_W3);
    const int ncl = min(n_nodes, NMAX);
    if (tid < 128) {
        int half = tid >> 6, e = tid & 63;
        int ec = e < nv ? e : (nv - 1);
        int pos = half * n_edges + tile + ec;
        long long node = is64 ? ei64[pos] : (long long)ei32[pos];
        node = node < 0 ? 0 : (node >= ncl ? (long long)ncl - 1 : node);
        sids[tid] = (int)node;
        b2s[tid] = __ldg(b2 + tid);
        w3s[tid] = __ldg(W3 + tid);
    }

    // stage full W2 (two 64-k chunks) — overlaps the P/Q gather below
#pragma unroll
    for (int c = 0; c < 2; c++) {
        uint32_t base = sb + SM_W + (uint32_t)c * WCHUNK;
        int col0 = c * 64;
#pragma unroll
        for (int it = 0; it < 4; it++) {
            int idx = tid + it * THREADS;
            int n = idx >> 3, j = idx & 7;
            cp16(base + n * SWS + j * 16, g_w2t_hi + n * 128 + col0 + j * 8);
            cp16(base + WLO_OFF + n * SWS + j * 16, g_w2t_lo + n * 128 + col0 + j * 8);
        }
    }
    cp_commit();
    __syncthreads();   // sids visible

    // ---- gather P[src] + Q[tgt], elu, split to bf16 hi/lo in A region ----
    const float4* Pp = reinterpret_cast<const float4*>(g_P);
    const float4* Qp = reinterpret_cast<const float4*>(g_Q);
#pragma unroll
    for (int it = 0; it < 8; it++) {
        int v = tid + it * THREADS;        // 0..2047 quads (64e x 32q)
        int e = v >> 5, q = v & 31;
        float4 p = __ldg(Pp + sids[e] * 32 + q);
        float4 r = __ldg(Qp + sids[64 + e] * 32 + q);
        BF4 h, l;
        split_bf16(elu1(p.x + r.x), h.b[0], l.b[0]);
        split_bf16(elu1(p.y + r.y), h.b[1], l.b[1]);
        split_bf16(elu1(p.z + r.z), h.b[2], l.b[2]);
        split_bf16(elu1(p.w + r.w), h.b[3], l.b[3]);
        uint32_t dst = e * SA2 + q * 8;
        *reinterpret_cast<unsigned long long*>(smem + SM_A_HI + dst) = h.u;
        *reinterpret_cast<unsigned long long*>(smem + SM_A_LO + dst) = l.u;
    }
    cp_wait0();
    __syncthreads();

    float acc[2][4][4];
#pragma unroll
    for (int m = 0; m < 2; m++)
#pragma unroll
        for (int j = 0; j < 4; j++)
#pragma unroll
            for (int q = 0; q < 4; q++) acc[m][j][q] = 0.0f;

    // ---- layer 2: both 64-k chunks resident, no barrier in between ----
    gemm_chunk(sb + SM_A_HI, sb + SM_A_LO, SA2, 0,   sb + SM_W,          e0, n0, lane, acc);
    gemm_chunk(sb + SM_A_HI, sb + SM_A_LO, SA2, 128, sb + SM_W + WCHUNK, e0, n0, lane, acc);

    // ---- epilogue: bias + elu + dot(W3), butterfly over tig ----
    float pa[2] = {0.0f, 0.0f}, pb[2] = {0.0f, 0.0f};
#pragma unroll
    for (int mt = 0; mt < 2; mt++) {
#pragma unroll
        for (int nt = 0; nt < 4; nt++) {
            int nc = n0 + 8 * nt + 2 * tig;
            float w0 = w3s[nc], w1 = w3s[nc + 1];
            pa[mt] += elu1(acc[mt][nt][0] + b2s[nc]) * w0
                    + elu1(acc[mt][nt][1] + b2s[nc + 1]) * w1;
            pb[mt] += elu1(acc[mt][nt][2] + b2s[nc]) * w0
                    + elu1(acc[mt][nt][3] + b2s[nc + 1]) * w1;
        }
    }
#pragma unroll
    for (int mt = 0; mt < 2; mt++) {
        pa[mt] += __shfl_xor_sync(0xffffffff, pa[mt], 1);
        pa[mt] += __shfl_xor_sync(0xffffffff, pa[mt], 2);
        pb[mt] += __shfl_xor_sync(0xffffffff, pb[mt], 1);
        pb[mt] += __shfl_xor_sync(0xffffffff, pb[mt], 2);
    }
    float* red = (float*)(smem + SM_RED) + nw * 64;
    if (tig == 0) {
#pragma unroll
        for (int mt = 0; mt < 2; mt++) {
            red[e0 + 16 * mt + gid] = pa[mt];
            red[e0 + 16 * mt + gid + 8] = pb[mt];
        }
    }
    __syncthreads();
    if (tid < 64 && tid < nv) {
        float* r = (float*)(smem + SM_RED);
        out[tile + tid] = r[tid] + r[64 + tid] + r[128 + tid] + r[192 + tid] + __ldg(b3);
    }
}

extern "C" void kernel_launch(void* const* d_in, const int* in_sizes, int n_in,
                              void* d_out, int out_size) {
    const float* x  = (const float*)d_in[0];
    const void*  ei = d_in[1];
    const float* W1 = (const float*)d_in[2];
    const float* b1 = (const float*)d_in[3];
    const float* W2 = (const float*)d_in[4];
    const float* b2 = (const float*)d_in[5];
    const float* W3 = (const float*)d_in[6];
    const float* b3 = (const float*)d_in[7];
    float* out = (float*)d_out;

    const int n_edges = out_size;
    const int n_nodes = in_sizes[0] / 128;
    const int ncl = n_nodes < NMAX ? n_nodes : NMAX;
    const int n4 = ncl * 128 / 4;
    const int ntiles = (ncl + 63) / 64;

    cudaFuncSetAttribute(pq_kernel,
                         cudaFuncAttributeMaxDynamicSharedMemorySize, SMEM_BYTES);
    cudaFuncSetAttribute(edge_mlp_hmma_kernel,
                         cudaFuncAttributeMaxDynamicSharedMemorySize, SMEM_BYTES);

    wconv_kernel<<<192, 256>>>(W1, W2, (const int*)ei);
    xsplit_kernel<<<(n4 + 255) / 256, 256>>>(x, n4);
    pq_kernel<<<ntiles * 2, THREADS, SMEM_BYTES>>>(b1, n_nodes);
    const int grid = (n_edges + EPT - 1) / EPT;
    edge_mlp_hmma_kernel<<<grid, THREADS, SMEM_BYTES>>>(ei, b2, W3, b3,
                                                        out, n_edges, n_nodes);
}

// round 17
// speedup vs baseline: 1.8447x; 1.1047x over previous
#include <cuda_runtime.h>
#include <cuda_bf16.h>
#include <math.h>
#include <stdint.h>

// ---------------------------------------------------------------------------
// EdgeMLPMPN, R17 = R16 + persistent main kernel.
//   P = x @ W1[0:128] + b1,  Q = x @ W1[128:256]      (per node, prologue)
//   h1 = elu(P[src] + Q[tgt])                          (per edge, gather+add)
//   h2 = elu(h1 @ W2 + b2); out = h2 @ W3 + b3         (per edge, bf16x3 HMMA)
// Main kernel: grid=304 persistent CTAs (2/SM); W2 staged ONCE per CTA;
// next tile's edge indices prefetched into a double-buffered sids region.
// EPT=64, 8 warps (2m x 4n) per CTA.
// ---------------------------------------------------------------------------

#define EPT 64
#define THREADS 256
#define NMAX 100000
#define SA2 272    // A/h1 row stride (128 bf16 + 16B pad)
#define SWS 144    // W chunk row stride (64 bf16 + 16B pad)

#define SM_A_HI 0
#define SM_A_LO 17408
#define SM_W    34816                  // chunk c: hi @ +c*36864, lo @ hi+18432
#define WCHUNK  36864
#define WLO_OFF 18432
#define SM_CTRL 108544
#define SM_SIDS (SM_CTRL)              // 2 x 128 ints (double buffer)
#define SM_B2   (SM_CTRL + 1024)
#define SM_W3   (SM_B2 + 512)
#define SM_RED  (SM_W3 + 512)          // 4 x 64 floats
#define SMEM_BYTES (SM_RED + 1024)     // 111616 B -> 2 CTAs/SM

#define MAIN_GRID 304                  // 2 per SM on 152 SMs

__device__ int g_is64;
__device__ __align__(16) __nv_bfloat16 g_x_hi[NMAX * 128];
__device__ __align__(16) __nv_bfloat16 g_x_lo[NMAX * 128];
__device__ __align__(16) __nv_bfloat16 g_w1t_hi[128 * 256];
__device__ __align__(16) __nv_bfloat16 g_w1t_lo[128 * 256];
__device__ __align__(16) __nv_bfloat16 g_w2t_hi[128 * 128];
__device__ __align__(16) __nv_bfloat16 g_w2t_lo[128 * 128];
__device__ __align__(16) float g_P[NMAX * 128];   // x@W1a + b1
__device__ __align__(16) float g_Q[NMAX * 128];   // x@W1b

__device__ __forceinline__ uint32_t smem_u32(const void* p) {
    uint32_t a;
    asm("{ .reg .u64 t; cvta.to.shared.u64 t, %1; cvt.u32.u64 %0, t; }" : "=r"(a) : "l"(p));
    return a;
}
__device__ __forceinline__ void ldm_x4(uint32_t addr, uint32_t r[4]) {
    asm volatile("ldmatrix.sync.aligned.m8n8.x4.shared.b16 {%0,%1,%2,%3}, [%4];"
                 : "=r"(r[0]), "=r"(r[1]), "=r"(r[2]), "=r"(r[3]) : "r"(addr));
}
__device__ __forceinline__ void hmma(float c[4], const uint32_t a[4],
                                     uint32_t b0, uint32_t b1) {
    asm volatile(
        "mma.sync.aligned.m16n8k16.row.col.f32.bf16.bf16.f32 "
        "{%0,%1,%2,%3}, {%4,%5,%6,%7}, {%8,%9}, {%0,%1,%2,%3};"
        : "+f"(c[0]), "+f"(c[1]), "+f"(c[2]), "+f"(c[3])
        : "r"(a[0]), "r"(a[1]), "r"(a[2]), "r"(a[3]), "r"(b0), "r"(b1));
}
__device__ __forceinline__ void cp16(uint32_t dst, const void* src) {
    asm volatile("cp.async.cg.shared.global [%0], [%1], 16;" :: "r"(dst), "l"(src));
}
__device__ __forceinline__ void cp_commit() {
    asm volatile("cp.async.commit_group;" ::: "memory");
}
__device__ __forceinline__ void cp_wait0() {
    asm volatile("cp.async.wait_group 0;" ::: "memory");
}
__device__ __forceinline__ float elu1(float v) {
    return v > 0.0f ? v : (__expf(v) - 1.0f);
}
__device__ __forceinline__ void split_bf16(float v, __nv_bfloat16& hi, __nv_bfloat16& lo) {
    hi = __float2bfloat16_rn(v);
    lo = __float2bfloat16_rn(v - __bfloat162float(hi));
}
union BF4 { __nv_bfloat16 b[4]; unsigned long long u; };
union BF2 { __nv_bfloat16 b[2]; uint32_t u; };

// ---------------- prologue A: split x into bf16 hi/lo ----------------
__global__ void xsplit_kernel(const float* __restrict__ x, int n4) {
    int i = blockIdx.x * blockDim.x + threadIdx.x;
    if (i >= n4) return;
    float4 v = __ldg(reinterpret_cast<const float4*>(x) + i);
    BF4 h, l;
    split_bf16(v.x, h.b[0], l.b[0]);
    split_bf16(v.y, h.b[1], l.b[1]);
    split_bf16(v.z, h.b[2], l.b[2]);
    split_bf16(v.w, h.b[3], l.b[3]);
    *reinterpret_cast<unsigned long long*>(g_x_hi + i * 4) = h.u;
    *reinterpret_cast<unsigned long long*>(g_x_lo + i * 4) = l.u;
}

// ---------------- prologue B: transpose + split W1, W2; sniff ei dtype ----
__global__ void wconv_kernel(const float* __restrict__ W1, const float* __restrict__ W2,
                             const int* __restrict__ ei32) {
    int i = blockIdx.x * blockDim.x + threadIdx.x;
    if (i == 0) {
        int odd_or = 0;
#pragma unroll
        for (int j = 1; j < 64; j += 2) odd_or |= ei32[j];
        g_is64 = (odd_or == 0) ? 1 : 0;
    }
    if (i < 32768) {                     // W1T[n][k] <- W1[k][n]
        int n = i >> 8, k = i & 255;
        float v = __ldg(W1 + k * 128 + n);
        __nv_bfloat16 h, l; split_bf16(v, h, l);
        g_w1t_hi[i] = h; g_w1t_lo[i] = l;
    } else if (i < 49152) {              // W2T[n][k] <- W2[k][n]
        int j = i - 32768;
        int n = j >> 7, k = j & 127;
        float v = __ldg(W2 + k * 128 + n);
        __nv_bfloat16 h, l; split_bf16(v, h, l);
        g_w2t_hi[j] = h; g_w2t_lo[j] = l;
    }
}

// shared: one 64-k chunk (4 k-tiles); warp tile 2m x 4n; pass-major schedule.
__device__ __forceinline__ void gemm_chunk(uint32_t aH, uint32_t aL, int sa,
                                           int a_k0byte, uint32_t wHi,
                                           int e0, int n0, int lane,
                                           float acc[2][4][4]) {
    const int rowA = lane & 15;
    const int chA = (lane >> 4) * 16;
    const int rowB = (lane & 7) + ((lane >> 4) << 3);
    const int chB = ((lane >> 3) & 1) * 16;

    uint32_t aH0 = aH + (e0 + rowA) * sa + chA + a_k0byte;
    uint32_t aH1 = aH0 + 16 * sa;
    uint32_t aL0 = aL + (e0 + rowA) * sa + chA + a_k0byte;
    uint32_t aL1 = aL0 + 16 * sa;
    uint32_t bH0 = wHi + (n0 + rowB) * SWS + chB;
    uint32_t bH1 = bH0 + 16 * SWS;
    uint32_t bL0 = bH0 + WLO_OFF;
    uint32_t bL1 = bL0 + 16 * SWS;

#pragma unroll
    for (int kt = 0; kt < 4; kt++) {
        uint32_t ah0[4], ah1[4], al0[4], al1[4];
        ldm_x4(aH0 + kt * 32, ah0);
        ldm_x4(aH1 + kt * 32, ah1);
        ldm_x4(aL0 + kt * 32, al0);
        ldm_x4(aL1 + kt * 32, al1);
        uint32_t bh0[4], bh1[4], bl0[4], bl1[4];
        ldm_x4(bH0 + kt * 32, bh0);
        ldm_x4(bH1 + kt * 32, bh1);
        ldm_x4(bL0 + kt * 32, bl0);
        ldm_x4(bL1 + kt * 32, bl1);
        hmma(acc[0][0], ah0, bh0[0], bh0[1]);
        hmma(acc[0][1], ah0, bh0[2], bh0[3]);
        hmma(acc[0][2], ah0, bh1[0], bh1[1]);
        hmma(acc[0][3], ah0, bh1[2], bh1[3]);
        hmma(acc[1][0], ah1, bh0[0], bh0[1]);
        hmma(acc[1][1], ah1, bh0[2], bh0[3]);
        hmma(acc[1][2], ah1, bh1[0], bh1[1]);
        hmma(acc[1][3], ah1, bh1[2], bh1[3]);
        hmma(acc[0][0], ah0, bl0[0], bl0[1]);
        hmma(acc[0][1], ah0, bl0[2], bl0[3]);
        hmma(acc[0][2], ah0, bl1[0], bl1[1]);
        hmma(acc[0][3], ah0, bl1[2], bl1[3]);
        hmma(acc[1][0], ah1, bl0[0], bl0[1]);
        hmma(acc[1][1], ah1, bl0[2], bl0[3]);
        hmma(acc[1][2], ah1, bl1[0], bl1[1]);
        hmma(acc[1][3], ah1, bl1[2], bl1[3]);
        hmma(acc[0][0], al0, bh0[0], bh0[1]);
        hmma(acc[0][1], al0, bh0[2], bh0[3]);
        hmma(acc[0][2], al0, bh1[0], bh1[1]);
        hmma(acc[0][3], al0, bh1[2], bh1[3]);
        hmma(acc[1][0], al1, bh0[0], bh0[1]);
        hmma(acc[1][1], al1, bh0[2], bh0[3]);
        hmma(acc[1][2], al1, bh1[0], bh1[1]);
        hmma(acc[1][3], al1, bh1[2], bh1[3]);
    }
}

// ---------------- prologue C: P = x@W1a + b1, Q = x@W1b (per node) ----------
__global__ void __launch_bounds__(THREADS, 2)
pq_kernel(const float* __restrict__ b1, int n_nodes) {
    extern __shared__ char smem[];
    const uint32_t sb = smem_u32(smem);
    const int tid = threadIdx.x, wid = tid >> 5, lane = tid & 31;
    const int gid = lane >> 2, tig = lane & 3;
    const int mw = wid >> 2, nw = wid & 3;
    const int e0 = mw * 32, n0 = nw * 32;
    const int sel = blockIdx.x & 1;        // 0 -> P, 1 -> Q
    const int tile = blockIdx.x >> 1;
    const int node0 = tile * 64;
    const int ncl = min(n_nodes, NMAX);

    float* b1s = (float*)(smem + SM_SIDS);
    if (tid < 128) b1s[tid] = sel ? 0.0f : __ldg(b1 + tid);

    // stage A: 64 node rows of x (hi/lo), full 256B per row
#pragma unroll
    for (int it = 0; it < 4; it++) {
        int idx = tid + it * THREADS;      // 0..1023
        int e = idx >> 4, j = idx & 15;
        int node = node0 + e;
        node = node < ncl ? node : (ncl - 1);
        int src = node * 128 + j * 8;
        uint32_t dst = e * SA2 + j * 16;
        cp16(sb + SM_A_HI + dst, g_x_hi + src);
        cp16(sb + SM_A_LO + dst, g_x_lo + src);
    }
    // stage W1 half 'sel' as two 64-k chunks
#pragma unroll
    for (int c = 0; c < 2; c++) {
        uint32_t base = sb + SM_W + (uint32_t)c * WCHUNK;
        int col0 = sel * 128 + c * 64;
#pragma unroll
        for (int it = 0; it < 4; it++) {
            int idx = tid + it * THREADS;
            int n = idx >> 3, j = idx & 7;
            cp16(base + n * SWS + j * 16, g_w1t_hi + n * 256 + col0 + j * 8);
            cp16(base + WLO_OFF + n * SWS + j * 16, g_w1t_lo + n * 256 + col0 + j * 8);
        }
    }
    cp_commit();
    cp_wait0();
    __syncthreads();

    float acc[2][4][4];
#pragma unroll
    for (int m = 0; m < 2; m++)
#pragma unroll
        for (int j = 0; j < 4; j++)
#pragma unroll
            for (int q = 0; q < 4; q++) acc[m][j][q] = 0.0f;

    gemm_chunk(sb + SM_A_HI, sb + SM_A_LO, SA2, 0,   sb + SM_W,          e0, n0, lane, acc);
    gemm_chunk(sb + SM_A_HI, sb + SM_A_LO, SA2, 128, sb + SM_W + WCHUNK, e0, n0, lane, acc);

    float* outg = sel ? g_Q : g_P;
#pragma unroll
    for (int mt = 0; mt < 2; mt++) {
#pragma unroll
        for (int nt = 0; nt < 4; nt++) {
            int nc = n0 + 8 * nt + 2 * tig;
            int ra = e0 + 16 * mt + gid, rb = ra + 8;
            int ga = node0 + ra, gb = node0 + rb;
            if (ga < ncl) {
                outg[ga * 128 + nc]     = acc[mt][nt][0] + b1s[nc];
                outg[ga * 128 + nc + 1] = acc[mt][nt][1] + b1s[nc + 1];
            }
            if (gb < ncl) {
                outg[gb * 128 + nc]     = acc[mt][nt][2] + b1s[nc];
                outg[gb * 128 + nc + 1] = acc[mt][nt][3] + b1s[nc + 1];
            }
        }
    }
}

// ---------------- main: persistent; h1 = elu(P[src]+Q[tgt]); layers 2,3 -----
__global__ void __launch_bounds__(THREADS, 2)
edge_mlp_hmma_kernel(const void* __restrict__ ei,
                     const float* __restrict__ b2,
                     const float* __restrict__ W3, const float* __restrict__ b3,
                     float* __restrict__ out, int n_edges, int n_nodes) {
    extern __shared__ char smem[];
    const uint32_t sb = smem_u32(smem);
    const int tid = threadIdx.x, wid = tid >> 5, lane = tid & 31;
    const int gid = lane >> 2, tig = lane & 3;
    const int mw = wid >> 2, nw = wid & 3;
    const int e0 = mw * 32, n0 = nw * 32;
    const int ntiles = (n_edges + EPT - 1) / EPT;

    const bool is64 = (g_is64 != 0);
    const int* ei32 = (const int*)ei;
    const long long* ei64 = (const long long*)ei;
    const int ncl = min(n_nodes, NMAX);

    int* sids = (int*)(smem + SM_SIDS);      // 2 x 128 ints
    float* b2s = (float*)(smem + SM_B2);
    float* w3s = (float*)(smem + SM_W3);
    const float b3v = __ldg(b3);

    // one-time: constants + W2 (both 64-k chunks) staged via cp.async
    if (tid < 128) {
        b2s[tid] = __ldg(b2 + tid);
        w3s[tid] = __ldg(W3 + tid);
    }
#pragma unroll
    for (int c = 0; c < 2; c++) {
        uint32_t base = sb + SM_W + (uint32_t)c * WCHUNK;
        int col0 = c * 64;
#pragma unroll
        for (int it = 0; it < 4; it++) {
            int idx = tid + it * THREADS;
            int n = idx >> 3, j = idx & 7;
            cp16(base + n * SWS + j * 16, g_w2t_hi + n * 128 + col0 + j * 8);
            cp16(base + WLO_OFF + n * SWS + j * 16, g_w2t_lo + n * 128 + col0 + j * 8);
        }
    }
    cp_commit();

    // sids for the first tile -> buffer 0
    const int t0 = blockIdx.x;
    if (t0 < ntiles && tid < 128) {
        int half = tid >> 6, e = tid & 63;
        int tile = t0 * EPT;
        int nv = min(EPT, n_edges - tile);
        int ec = e < nv ? e : (nv - 1);
        int pos = half * n_edges + tile + ec;
        long long node = is64 ? ei64[pos] : (long long)ei32[pos];
        node = node < 0 ? 0 : (node >= ncl ? (long long)ncl - 1 : node);
        sids[tid] = (int)node;
    }
    __syncthreads();   // sids buf0 + constants visible

    const float4* Pp = reinterpret_cast<const float4*>(g_P);
    const float4* Qp = reinterpret_cast<const float4*>(g_Q);
    int sbuf = 0;
    bool first = true;

    for (int t = t0; t < ntiles; t += MAIN_GRID) {
        const int tile = t * EPT;
        const int nv = min(EPT, n_edges - tile);
        const int* sc = sids + sbuf * 128;

        // ---- gather P[src] + Q[tgt], elu, split into A region ----
#pragma unroll
        for (int it = 0; it < 8; it++) {
            int v = tid + it * THREADS;        // 0..2047 quads (64e x 32q)
            int e = v >> 5, q = v & 31;
            float4 p = __ldg(Pp + sc[e] * 32 + q);
            float4 r = __ldg(Qp + sc[64 + e] * 32 + q);
            BF4 h, l;
            split_bf16(elu1(p.x + r.x), h.b[0], l.b[0]);
            split_bf16(elu1(p.y + r.y), h.b[1], l.b[1]);
            split_bf16(elu1(p.z + r.z), h.b[2], l.b[2]);
            split_bf16(elu1(p.w + r.w), h.b[3], l.b[3]);
            uint32_t dst = e * SA2 + q * 8;
            *reinterpret_cast<unsigned long long*>(smem + SM_A_HI + dst) = h.u;
            *reinterpret_cast<unsigned long long*>(smem + SM_A_LO + dst) = l.u;
        }

        // ---- prefetch next tile's sids into the other buffer ----
        int tn = t + MAIN_GRID;
        if (tn < ntiles && tid < 128) {
            int half = tid >> 6, e = tid & 63;
            int tile2 = tn * EPT;
            int nv2 = min(EPT, n_edges - tile2);
            int ec = e < nv2 ? e : (nv2 - 1);
            int pos = half * n_edges + tile2 + ec;
            long long node = is64 ? ei64[pos] : (long long)ei32[pos];
            node = node < 0 ? 0 : (node >= ncl ? (long long)ncl - 1 : node);
            sids[(sbuf ^ 1) * 128 + tid] = (int)node;
        }

        if (first) { cp_wait0(); first = false; }   // W2 resident
        __syncthreads();   // A visible; sids-next visible for next iter

        float acc[2][4][4];
#pragma unroll
        for (int m = 0; m < 2; m++)
#pragma unroll
            for (int j = 0; j < 4; j++)
#pragma unroll
                for (int q = 0; q < 4; q++) acc[m][j][q] = 0.0f;

        gemm_chunk(sb + SM_A_HI, sb + SM_A_LO, SA2, 0,   sb + SM_W,          e0, n0, lane, acc);
        gemm_chunk(sb + SM_A_HI, sb + SM_A_LO, SA2, 128, sb + SM_W + WCHUNK, e0, n0, lane, acc);

        // ---- epilogue: bias + elu + dot(W3), butterfly over tig ----
        float pa[2] = {0.0f, 0.0f}, pb[2] = {0.0f, 0.0f};
#pragma unroll
        for (int mt = 0; mt < 2; mt++) {
#pragma unroll
            for (int nt = 0; nt < 4; nt++) {
                int nc = n0 + 8 * nt + 2 * tig;
                float w0 = w3s[nc], w1 = w3s[nc + 1];
                pa[mt] += elu1(acc[mt][nt][0] + b2s[nc]) * w0
                        + elu1(acc[mt][nt][1] + b2s[nc + 1]) * w1;
                pb[mt] += elu1(acc[mt][nt][2] + b2s[nc]) * w0
                        + elu1(acc[mt][nt][3] + b2s[nc + 1]) * w1;
            }
        }
#pragma unroll
        for (int mt = 0; mt < 2; mt++) {
            pa[mt] += __shfl_xor_sync(0xffffffff, pa[mt], 1);
            pa[mt] += __shfl_xor_sync(0xffffffff, pa[mt], 2);
            pb[mt] += __shfl_xor_sync(0xffffffff, pb[mt], 1);
            pb[mt] += __shfl_xor_sync(0xffffffff, pb[mt], 2);
        }
        float* red = (float*)(smem + SM_RED) + nw * 64;
        if (tig == 0) {
#pragma unroll
            for (int mt = 0; mt < 2; mt++) {
                red[e0 + 16 * mt + gid] = pa[mt];
                red[e0 + 16 * mt + gid + 8] = pb[mt];
            }
        }
        __syncthreads();   // red visible; GEMM reads of A done -> A reusable
        if (tid < 64 && tid < nv) {
            float* r = (float*)(smem + SM_RED);
            out[tile + tid] = r[tid] + r[64 + tid] + r[128 + tid] + r[192 + tid] + b3v;
        }
        sbuf ^= 1;
    }
}

extern "C" void kernel_launch(void* const* d_in, const int* in_sizes, int n_in,
                              void* d_out, int out_size) {
    const float* x  = (const float*)d_in[0];
    const void*  ei = d_in[1];
    const float* W1 = (const float*)d_in[2];
    const float* b1 = (const float*)d_in[3];
    const float* W2 = (const float*)d_in[4];
    const float* b2 = (const float*)d_in[5];
    const float* W3 = (const float*)d_in[6];
    const float* b3 = (const float*)d_in[7];
    float* out = (float*)d_out;

    const int n_edges = out_size;
    const int n_nodes = in_sizes[0] / 128;
    const int ncl = n_nodes < NMAX ? n_nodes : NMAX;
    const int n4 = ncl * 128 / 4;
    const int ntiles_pq = (ncl + 63) / 64;
    const int ntiles_main = (n_edges + EPT - 1) / EPT;

    cudaFuncSetAttribute(pq_kernel,
                         cudaFuncAttributeMaxDynamicSharedMemorySize, SMEM_BYTES);
    cudaFuncSetAttribute(edge_mlp_hmma_kernel,
                         cudaFuncAttributeMaxDynamicSharedMemorySize, SMEM_BYTES);

    wconv_kernel<<<192, 256>>>(W1, W2, (const int*)ei);
    xsplit_kernel<<<(n4 + 255) / 256, 256>>>(x, n4);
    pq_kernel<<<ntiles_pq * 2, THREADS, SMEM_BYTES>>>(b1, n_nodes);
    const int grid = ntiles_main < MAIN_GRID ? ntiles_main : MAIN_GRID;
    edge_mlp_hmma_kernel<<<grid, THREADS, SMEM_BYTES>>>(ei, b2, W3, b3,
                                                        out, n_edges, n_nodes);
}